// round 11
// baseline (speedup 1.0000x reference)
#include <cuda_runtime.h>
#include <cuda_fp16.h>
#include <math.h>
#include <stdint.h>

#define N_NODES 50000
#define N_EDGES 800000
#define E_TOT   (N_EDGES + N_NODES)
#define FDIM    512
#define HEADS   8
#define HID     64
#define NEG_SLOPE 0.2f

#define KP0 128
#define WOFF0 0
#define WOFF1 (FDIM * KP0)
#define WOFF2 (WOFF1 + FDIM * FDIM)
#define WTOT  (WOFF2 + FDIM * FDIM)

// ---------------- scratch (device globals; no allocs allowed) ----------------
__device__ float  g_hA[(size_t)N_NODES * FDIM];
__device__ __half g_Ahi[(size_t)N_NODES * FDIM];
__device__ __half g_Alo[(size_t)N_NODES * FDIM];
__device__ __half g_Wthi[WTOT];
__device__ __half g_Wtlo[WTOT];
__device__ float  g_asrc[N_NODES * HEADS];
__device__ float  g_adst[N_NODES * HEADS];
__device__ int    g_deg[N_NODES];
__device__ int    g_rowptr[N_NODES + 1];
__device__ int    g_rowcur[N_NODES];
__device__ int    g_srclist[E_TOT];

// ============================ helpers ============================
__device__ __forceinline__ uint32_t smem_u32(const void* p) {
    uint32_t a;
    asm("{ .reg .u64 t; cvta.to.shared.u64 t, %1; cvt.u32.u64 %0, t; }" : "=r"(a) : "l"(p));
    return a;
}
__device__ __forceinline__ void mma_f16(float* d, const uint32_t* a, const uint32_t* b) {
    asm volatile(
        "mma.sync.aligned.m16n8k16.row.col.f32.f16.f16.f32 "
        "{%0,%1,%2,%3}, {%4,%5,%6,%7}, {%8,%9}, {%0,%1,%2,%3};"
        : "+f"(d[0]), "+f"(d[1]), "+f"(d[2]), "+f"(d[3])
        : "r"(a[0]), "r"(a[1]), "r"(a[2]), "r"(a[3]), "r"(b[0]), "r"(b[1]));
}
__device__ __forceinline__ void ldsm_x4(uint32_t& r0, uint32_t& r1, uint32_t& r2,
                                        uint32_t& r3, uint32_t addr) {
    asm volatile("ldmatrix.sync.aligned.m8n8.x4.shared.b16 {%0,%1,%2,%3}, [%4];"
                 : "=r"(r0), "=r"(r1), "=r"(r2), "=r"(r3) : "r"(addr));
}
__device__ __forceinline__ void cp_async16(uint32_t saddr, const void* gaddr, int src_bytes) {
    asm volatile("cp.async.cg.shared.global [%0], [%1], 16, %2;"
                 :: "r"(saddr), "l"(gaddr), "r"(src_bytes));
}
#define CP_COMMIT() asm volatile("cp.async.commit_group;" ::: "memory")
#define CP_WAIT(n)  asm volatile("cp.async.wait_group %0;" :: "n"(n) : "memory")

// ============================ CSR build ============================
__global__ void zero_deg_kernel() {
    int i = blockIdx.x * blockDim.x + threadIdx.x;
    if (i < N_NODES) g_deg[i] = 0;
}
__global__ void count_kernel(const int* __restrict__ ei) {
    int idx = blockIdx.x * blockDim.x + threadIdx.x;
    if (idx >= E_TOT) return;
    int dst = (idx < N_EDGES) ? ei[N_EDGES + idx] : (idx - N_EDGES);
    atomicAdd(&g_deg[dst], 1);
}
__global__ void scan_kernel() {
    __shared__ int sums[1024];
    const int per = (N_NODES + 1023) / 1024;
    int t  = threadIdx.x;
    int lo = t * per;
    int hi = min(lo + per, N_NODES);
    int s = 0;
    for (int i = lo; i < hi; i++) s += g_deg[i];
    sums[t] = s;
    __syncthreads();
    if (t == 0) {
        int run = 0;
        for (int i = 0; i < 1024; i++) { int v = sums[i]; sums[i] = run; run += v; }
        g_rowptr[N_NODES] = run;
    }
    __syncthreads();
    int run = sums[t];
    for (int i = lo; i < hi; i++) {
        g_rowptr[i] = run;
        g_rowcur[i] = run;
        run += g_deg[i];
    }
}
__global__ void fill_kernel(const int* __restrict__ ei) {
    int idx = blockIdx.x * blockDim.x + threadIdx.x;
    if (idx >= E_TOT) return;
    int src, dst;
    if (idx < N_EDGES) { src = ei[idx]; dst = ei[N_EDGES + idx]; }
    else               { src = dst = idx - N_EDGES; }
    int pos = atomicAdd(&g_rowcur[dst], 1);
    g_srclist[pos] = src;
}

// ============================ fp16 hi/lo conversions ============================
__global__ void convert_x_kernel(const float* __restrict__ x) {
    int idx = blockIdx.x * blockDim.x + threadIdx.x;
    if (idx >= N_NODES * KP0) return;
    int n = idx >> 7, k = idx & (KP0 - 1);
    float v = (k < 69) ? x[n * 69 + k] : 0.f;
    __half h = __float2half_rn(v);
    g_Ahi[idx] = h;
    g_Alo[idx] = __float2half_rn(v - __half2float(h));
}
// all three weights, transposed+padded into per-layer slices of g_Wthi/g_Wtlo
__global__ void convert_w_all_kernel(const float* __restrict__ W0,
                                     const float* __restrict__ W1,
                                     const float* __restrict__ W2) {
    int idx = blockIdx.x * blockDim.x + threadIdx.x;
    if (idx >= WTOT) return;
    const float* W;
    int K, Kp, off;
    if (idx < WOFF1)      { W = W0; K = 69;   Kp = KP0;  off = 0; }
    else if (idx < WOFF2) { W = W1; K = FDIM; Kp = FDIM; off = WOFF1; }
    else                  { W = W2; K = FDIM; Kp = FDIM; off = WOFF2; }
    int li = idx - off;
    int n = li / Kp, k = li % Kp;
    float v = (k < K) ? W[(size_t)k * FDIM + n] : 0.f;
    __half h = __float2half_rn(v);
    g_Wthi[idx] = h;
    g_Wtlo[idx] = __float2half_rn(v - __half2float(h));
}

// ============================ fp16 3-term warp-MMA GEMM + fused alpha ============
#define BM 128
#define BN 128
#define BK 64
#define TSTRIDE 72
#define TILE_HALFS (128 * TSTRIDE)
#define BUF_HALFS (4 * TILE_HALFS)
#define SMEM_GEMM (2 * BUF_HALFS * 2 + 128 * 4 * 4)

__global__ __launch_bounds__(256, 1) void mma_gemm_kernel(
    const __half* __restrict__ Ahi, const __half* __restrict__ Alo,
    const __half* __restrict__ Bhi, const __half* __restrict__ Blo,
    float* __restrict__ C, const float* __restrict__ aSrc, const float* __restrict__ aDst,
    int nrows, int Kp)
{
    extern __shared__ __half smh[];
    float* salpha = (float*)(smh + 2 * BUF_HALFS);   // [128][2 heads][2 (src,dst)]

    const int tid  = threadIdx.x;
    const int wid  = tid >> 5;
    const int lane = tid & 31;
    const int gid  = lane >> 2;
    const int tig  = lane & 3;
    const int warp_m = wid >> 2;
    const int warp_n = wid & 3;
    const int rowBase = blockIdx.y * BM;
    const int nBase   = blockIdx.x * BN;

    const int nch = Kp / BK;

    float acc[4][4][4];
#pragma unroll
    for (int i = 0; i < 4; i++)
#pragma unroll
        for (int j = 0; j < 4; j++)
#pragma unroll
            for (int q = 0; q < 4; q++) acc[i][j][q] = 0.f;

    const int lrow = tid >> 1, lseg = tid & 1;
    const int arow = rowBase + lrow;
    const int aok  = (arow < nrows) ? 16 : 0;
    const __half* gAhi = Ahi + (size_t)(aok ? arow : 0) * Kp + lseg * 32;
    const __half* gAlo = Alo + (size_t)(aok ? arow : 0) * Kp + lseg * 32;
    const __half* gBhi = Bhi + (size_t)(nBase + lrow) * Kp + lseg * 32;
    const __half* gBlo = Blo + (size_t)(nBase + lrow) * Kp + lseg * 32;
    const uint32_t sbase = smem_u32(smh);
    const uint32_t sdst = sbase + (lrow * TSTRIDE + lseg * 32) * 2;

    const int aoff = ((warp_m * 64 + (lane & 15)) * TSTRIDE + (lane >> 4) * 8) * 2;
    const int boff = ((warp_n * 32 + (lane >> 4) * 8 + (lane & 7)) * TSTRIDE
                      + ((lane >> 3) & 1) * 8) * 2;

    auto loadChunk = [&](int ic, int buf) {
        const int k0 = ic * BK;
        const uint32_t b = sdst + buf * (BUF_HALFS * 2);
#pragma unroll
        for (int j = 0; j < 4; j++)
            cp_async16(b + j * 16, gAhi + k0 + j * 8, aok);
#pragma unroll
        for (int j = 0; j < 4; j++)
            cp_async16(b + TILE_HALFS * 2 + j * 16, gAlo + k0 + j * 8, aok);
#pragma unroll
        for (int j = 0; j < 4; j++)
            cp_async16(b + TILE_HALFS * 4 + j * 16, gBhi + k0 + j * 8, 16);
#pragma unroll
        for (int j = 0; j < 4; j++)
            cp_async16(b + TILE_HALFS * 6 + j * 16, gBlo + k0 + j * 8, 16);
        CP_COMMIT();
    };

    loadChunk(0, 0);
    if (tid < 128) {
        salpha[tid * 4 + 0] = 0.f; salpha[tid * 4 + 1] = 0.f;
        salpha[tid * 4 + 2] = 0.f; salpha[tid * 4 + 3] = 0.f;
    }

    for (int ic = 0; ic < nch; ic++) {
        if (ic + 1 < nch) { loadChunk(ic + 1, (ic + 1) & 1); CP_WAIT(1); }
        else              { CP_WAIT(0); }
        __syncthreads();

        const uint32_t asHb = sbase + (ic & 1) * (BUF_HALFS * 2);
        const uint32_t asLb = asHb + TILE_HALFS * 2;
        const uint32_t bsHb = asHb + 2 * TILE_HALFS * 2;
        const uint32_t bsLb = asHb + 3 * TILE_HALFS * 2;

#pragma unroll
        for (int kk = 0; kk < BK; kk += 16) {
            uint32_t ahi[4][4], alo[4][4], bhi[4][2], blo[4][2];
            ldsm_x4(bhi[0][0], bhi[0][1], bhi[1][0], bhi[1][1], bsHb + boff + kk * 2);
            ldsm_x4(bhi[2][0], bhi[2][1], bhi[3][0], bhi[3][1],
                    bsHb + boff + (16 * TSTRIDE + kk) * 2);
            ldsm_x4(blo[0][0], blo[0][1], blo[1][0], blo[1][1], bsLb + boff + kk * 2);
            ldsm_x4(blo[2][0], blo[2][1], blo[3][0], blo[3][1],
                    bsLb + boff + (16 * TSTRIDE + kk) * 2);
#pragma unroll
            for (int mt = 0; mt < 4; mt++) {
                ldsm_x4(ahi[mt][0], ahi[mt][1], ahi[mt][2], ahi[mt][3],
                        asHb + aoff + (mt * 16 * TSTRIDE + kk) * 2);
                ldsm_x4(alo[mt][0], alo[mt][1], alo[mt][2], alo[mt][3],
                        asLb + aoff + (mt * 16 * TSTRIDE + kk) * 2);
            }
#pragma unroll
            for (int mt = 0; mt < 4; mt++)
#pragma unroll
                for (int nt = 0; nt < 4; nt++)
                    mma_f16(acc[mt][nt], ahi[mt], bhi[nt]);
#pragma unroll
            for (int mt = 0; mt < 4; mt++)
#pragma unroll
                for (int nt = 0; nt < 4; nt++)
                    mma_f16(acc[mt][nt], ahi[mt], blo[nt]);
#pragma unroll
            for (int mt = 0; mt < 4; mt++)
#pragma unroll
                for (int nt = 0; nt < 4; nt++)
                    mma_f16(acc[mt][nt], alo[mt], bhi[nt]);
        }
        __syncthreads();
    }

    // ---- epilogue: store C + fused alpha partial dots ----
    const int hl = warp_n >> 1;
    float s1[4][2], s2[4][2];
#pragma unroll
    for (int mt = 0; mt < 4; mt++) { s1[mt][0]=0.f; s1[mt][1]=0.f; s2[mt][0]=0.f; s2[mt][1]=0.f; }

#pragma unroll
    for (int mt = 0; mt < 4; mt++) {
        int r0 = rowBase + warp_m * 64 + mt * 16 + gid;
        int r1 = r0 + 8;
#pragma unroll
        for (int nt = 0; nt < 4; nt++) {
            int col = nBase + warp_n * 32 + nt * 8 + 2 * tig;
            float2 aS2 = *(const float2*)(aSrc + col);
            float2 aD2 = *(const float2*)(aDst + col);
            if (r0 < nrows)
                *(float2*)(C + (size_t)r0 * FDIM + col) =
                    make_float2(acc[mt][nt][0], acc[mt][nt][1]);
            if (r1 < nrows)
                *(float2*)(C + (size_t)r1 * FDIM + col) =
                    make_float2(acc[mt][nt][2], acc[mt][nt][3]);
            s1[mt][0] += acc[mt][nt][0] * aS2.x + acc[mt][nt][1] * aS2.y;
            s2[mt][0] += acc[mt][nt][0] * aD2.x + acc[mt][nt][1] * aD2.y;
            s1[mt][1] += acc[mt][nt][2] * aS2.x + acc[mt][nt][3] * aS2.y;
            s2[mt][1] += acc[mt][nt][2] * aD2.x + acc[mt][nt][3] * aD2.y;
        }
    }
#pragma unroll
    for (int mt = 0; mt < 4; mt++)
#pragma unroll
        for (int j = 0; j < 2; j++) {
            s1[mt][j] += __shfl_down_sync(0xffffffffu, s1[mt][j], 2, 4);
            s1[mt][j] += __shfl_down_sync(0xffffffffu, s1[mt][j], 1, 4);
            s2[mt][j] += __shfl_down_sync(0xffffffffu, s2[mt][j], 2, 4);
            s2[mt][j] += __shfl_down_sync(0xffffffffu, s2[mt][j], 1, 4);
        }
    if (tig == 0) {
#pragma unroll
        for (int mt = 0; mt < 4; mt++) {
            int lr0 = warp_m * 64 + mt * 16 + gid;
            atomicAdd(&salpha[lr0 * 4 + hl * 2 + 0], s1[mt][0]);
            atomicAdd(&salpha[lr0 * 4 + hl * 2 + 1], s2[mt][0]);
            atomicAdd(&salpha[(lr0 + 8) * 4 + hl * 2 + 0], s1[mt][1]);
            atomicAdd(&salpha[(lr0 + 8) * 4 + hl * 2 + 1], s2[mt][1]);
        }
    }
    __syncthreads();
    if (tid < 128) {
        int grow = rowBase + tid;
        if (grow < nrows) {
            int hbase = (nBase >> 6);
            g_asrc[grow * HEADS + hbase]     = salpha[tid * 4 + 0];
            g_adst[grow * HEADS + hbase]     = salpha[tid * 4 + 1];
            g_asrc[grow * HEADS + hbase + 1] = salpha[tid * 4 + 2];
            g_adst[grow * HEADS + hbase + 1] = salpha[tid * 4 + 3];
        }
    }
}

// ---------------- dual-chain online-softmax aggregation ----------------
// Two independent softmax states over even/odd edges, merged at the end.
// mode 0: relu + write fp16 hi/lo. mode 1: fused prediction head -> out.
#define AGG_CHUNK 256
__global__ __launch_bounds__(128) void aggregate_kernel(
    const float* __restrict__ h, const float* __restrict__ bias,
    __half* __restrict__ outHi, __half* __restrict__ outLo,
    const float* __restrict__ predW, const float* __restrict__ predb,
    float* __restrict__ out, int mode)
{
    int d = blockIdx.x;
    int t = threadIdx.x;            // 128 threads, 4 channels each
    int head = t >> 4;
    int start = g_rowptr[d], end = g_rowptr[d + 1];
    float adst_v = g_adst[d * HEADS + head];

    __shared__ int ssrc[AGG_CHUNK];
    __shared__ float spred[3];

    float m0 = -INFINITY, den0 = 0.f;
    float m1 = -INFINITY, den1 = 0.f;
    float4 A0 = make_float4(0.f, 0.f, 0.f, 0.f);
    float4 A1 = A0;

    for (int base = start; base < end; base += AGG_CHUNK) {
        int cnt = min(AGG_CHUNK, end - base);
        __syncthreads();
        for (int i = t; i < cnt; i += 128) ssrc[i] = g_srclist[base + i];
        if (t < 3 && base == start) spred[t] = 0.f;
        __syncthreads();
        int i = 0;
#pragma unroll 2
        for (; i + 1 < cnt; i += 2) {
            int s0 = ssrc[i], s1v = ssrc[i + 1];
            float e0 = g_asrc[s0 * HEADS + head] + adst_v;
            float e1 = g_asrc[s1v * HEADS + head] + adst_v;
            e0 = (e0 > 0.f) ? e0 : NEG_SLOPE * e0;
            e1 = (e1 > 0.f) ? e1 : NEG_SLOPE * e1;
            const float4 hv0 = *(const float4*)(h + (size_t)s0 * FDIM + t * 4);
            const float4 hv1 = *(const float4*)(h + (size_t)s1v * FDIM + t * 4);
            if (e0 > m0) {
                float sc = __expf(m0 - e0);
                m0 = e0; den0 *= sc;
                A0.x *= sc; A0.y *= sc; A0.z *= sc; A0.w *= sc;
            }
            if (e1 > m1) {
                float sc = __expf(m1 - e1);
                m1 = e1; den1 *= sc;
                A1.x *= sc; A1.y *= sc; A1.z *= sc; A1.w *= sc;
            }
            float w0 = __expf(e0 - m0);
            float w1 = __expf(e1 - m1);
            den0 += w0; den1 += w1;
            A0.x += w0 * hv0.x; A0.y += w0 * hv0.y;
            A0.z += w0 * hv0.z; A0.w += w0 * hv0.w;
            A1.x += w1 * hv1.x; A1.y += w1 * hv1.y;
            A1.z += w1 * hv1.z; A1.w += w1 * hv1.w;
        }
        if (i < cnt) {
            int s0 = ssrc[i];
            float e0 = g_asrc[s0 * HEADS + head] + adst_v;
            e0 = (e0 > 0.f) ? e0 : NEG_SLOPE * e0;
            const float4 hv0 = *(const float4*)(h + (size_t)s0 * FDIM + t * 4);
            if (e0 > m0) {
                float sc = __expf(m0 - e0);
                m0 = e0; den0 *= sc;
                A0.x *= sc; A0.y *= sc; A0.z *= sc; A0.w *= sc;
            }
            float w0 = __expf(e0 - m0);
            den0 += w0;
            A0.x += w0 * hv0.x; A0.y += w0 * hv0.y;
            A0.z += w0 * hv0.z; A0.w += w0 * hv0.w;
        }
    }

    // merge the two chains (m0 > -inf always: self-loop guarantees >=1 edge)
    float M = fmaxf(m0, m1);
    float sc0 = __expf(m0 - M), sc1 = __expf(m1 - M);
    float denom = den0 * sc0 + den1 * sc1;
    float4 acc;
    acc.x = A0.x * sc0 + A1.x * sc1;
    acc.y = A0.y * sc0 + A1.y * sc1;
    acc.z = A0.z * sc0 + A1.z * sc1;
    acc.w = A0.w * sc0 + A1.w * sc1;

    float inv = 1.f / (denom + 1e-16f);
    float4 b4 = *(const float4*)(bias + t * 4);
    float4 o;
    o.x = acc.x * inv + b4.x; o.y = acc.y * inv + b4.y;
    o.z = acc.z * inv + b4.z; o.w = acc.w * inv + b4.w;

    if (mode == 0) {
        o.x = fmaxf(o.x, 0.f); o.y = fmaxf(o.y, 0.f);
        o.z = fmaxf(o.z, 0.f); o.w = fmaxf(o.w, 0.f);
        size_t idx = (size_t)d * FDIM + t * 4;
        __half hx = __float2half_rn(o.x), hy = __float2half_rn(o.y);
        __half hz = __float2half_rn(o.z), hw = __float2half_rn(o.w);
        __half2* ph = (__half2*)(outHi + idx);
        ph[0] = __halves2half2(hx, hy);
        ph[1] = __halves2half2(hz, hw);
        __half2* pl = (__half2*)(outLo + idx);
        pl[0] = __halves2half2(__float2half_rn(o.x - __half2float(hx)),
                               __float2half_rn(o.y - __half2float(hy)));
        pl[1] = __halves2half2(__float2half_rn(o.z - __half2float(hz)),
                               __float2half_rn(o.w - __half2float(hw)));
    } else {
        int c0 = t * 4;
        float p0 = o.x * predW[(c0+0)*3+0] + o.y * predW[(c0+1)*3+0]
                 + o.z * predW[(c0+2)*3+0] + o.w * predW[(c0+3)*3+0];
        float p1 = o.x * predW[(c0+0)*3+1] + o.y * predW[(c0+1)*3+1]
                 + o.z * predW[(c0+2)*3+1] + o.w * predW[(c0+3)*3+1];
        float p2 = o.x * predW[(c0+0)*3+2] + o.y * predW[(c0+1)*3+2]
                 + o.z * predW[(c0+2)*3+2] + o.w * predW[(c0+3)*3+2];
#pragma unroll
        for (int off = 16; off > 0; off >>= 1) {
            p0 += __shfl_down_sync(0xffffffffu, p0, off);
            p1 += __shfl_down_sync(0xffffffffu, p1, off);
            p2 += __shfl_down_sync(0xffffffffu, p2, off);
        }
        if ((t & 31) == 0) {
            atomicAdd(&spred[0], p0);
            atomicAdd(&spred[1], p1);
            atomicAdd(&spred[2], p2);
        }
        __syncthreads();
        if (t < 3) out[d * 3 + t] = spred[t] + predb[t];
    }
}

// ---------------- launch ----------------
extern "C" void kernel_launch(void* const* d_in, const int* in_sizes, int n_in,
                              void* d_out, int out_size)
{
    const float* x     = (const float*)d_in[0];   // [N,69]
    const int*   ei    = (const int*)  d_in[1];   // [2,E]
    const float* W[3]    = {(const float*)d_in[3],  (const float*)d_in[7],  (const float*)d_in[11]};
    const float* aS[3]   = {(const float*)d_in[4],  (const float*)d_in[8],  (const float*)d_in[12]};
    const float* aD[3]   = {(const float*)d_in[5],  (const float*)d_in[9],  (const float*)d_in[13]};
    const float* bb[3]   = {(const float*)d_in[6],  (const float*)d_in[10], (const float*)d_in[14]};
    const float* predW = (const float*)d_in[15];
    const float* predb = (const float*)d_in[16];
    float* out = (float*)d_out;

    float*  hA;  cudaGetSymbolAddress((void**)&hA,  g_hA);
    __half* Ahi; cudaGetSymbolAddress((void**)&Ahi, g_Ahi);
    __half* Alo; cudaGetSymbolAddress((void**)&Alo, g_Alo);
    __half* Whi; cudaGetSymbolAddress((void**)&Whi, g_Wthi);
    __half* Wlo; cudaGetSymbolAddress((void**)&Wlo, g_Wtlo);

    cudaFuncSetAttribute(mma_gemm_kernel,
                         cudaFuncAttributeMaxDynamicSharedMemorySize, SMEM_GEMM);

    const int  K_in[3] = {KP0, FDIM, FDIM};
    const int  woff[3] = {WOFF0, WOFF1, WOFF2};
    dim3 ggrid(FDIM / BN, (N_NODES + BM - 1) / BM);

    // launches 1-4: zero, convert_x, convert_w_all, GEMM layer 0 (GEMM = #4 for ncu)
    zero_deg_kernel<<<(N_NODES + 255) / 256, 256>>>();
    convert_x_kernel<<<(N_NODES * KP0 + 255) / 256, 256>>>(x);
    convert_w_all_kernel<<<(WTOT + 255) / 256, 256>>>(W[0], W[1], W[2]);
    mma_gemm_kernel<<<ggrid, 256, SMEM_GEMM>>>(Ahi, Alo, Whi + woff[0], Wlo + woff[0],
                                               hA, aS[0], aD[0], N_NODES, K_in[0]);
    // CSR build (needed only by aggregate)
    count_kernel<<<(E_TOT + 255) / 256, 256>>>(ei);
    scan_kernel<<<1, 1024>>>();
    fill_kernel<<<(E_TOT + 255) / 256, 256>>>(ei);

    aggregate_kernel<<<N_NODES, 128>>>(hA, bb[0], Ahi, Alo, predW, predb, out, 0);

    for (int l = 1; l < 3; l++) {
        mma_gemm_kernel<<<ggrid, 256, SMEM_GEMM>>>(Ahi, Alo, Whi + woff[l], Wlo + woff[l],
                                                   hA, aS[l], aD[l], N_NODES, K_in[l]);
        aggregate_kernel<<<N_NODES, 128>>>(hA, bb[l], Ahi, Alo,
                                           predW, predb, out, (l == 2) ? 1 : 0);
    }
}

// round 12
// speedup vs baseline: 1.1342x; 1.1342x over previous
#include <cuda_runtime.h>
#include <cuda_fp16.h>
#include <math.h>
#include <stdint.h>

#define N_NODES 50000
#define N_EDGES 800000
#define E_TOT   (N_EDGES + N_NODES)
#define FDIM    512
#define HEADS   8
#define HID     64
#define NEG_SLOPE 0.2f

#define KP0 128
#define WOFF0 0
#define WOFF1 (FDIM * KP0)
#define WOFF2 (WOFF1 + FDIM * FDIM)
#define WTOT  (WOFF2 + FDIM * FDIM)

// ---------------- scratch (device globals; no allocs allowed) ----------------
__device__ float  g_hA[(size_t)N_NODES * FDIM];
__device__ __half g_Ahi[(size_t)N_NODES * FDIM];
__device__ __half g_Alo[(size_t)N_NODES * FDIM];
__device__ __half g_Wthi[WTOT];
__device__ __half g_Wtlo[WTOT];
__device__ float  g_asrc[N_NODES * HEADS];
__device__ float  g_adst[N_NODES * HEADS];
__device__ int    g_deg[N_NODES];
__device__ int    g_rowptr[N_NODES + 1];
__device__ int    g_rowcur[N_NODES];
__device__ int    g_srclist[E_TOT];

// ============================ helpers ============================
__device__ __forceinline__ uint32_t smem_u32(const void* p) {
    uint32_t a;
    asm("{ .reg .u64 t; cvta.to.shared.u64 t, %1; cvt.u32.u64 %0, t; }" : "=r"(a) : "l"(p));
    return a;
}
__device__ __forceinline__ void mma_f16(float* d, const uint32_t* a, const uint32_t* b) {
    asm volatile(
        "mma.sync.aligned.m16n8k16.row.col.f32.f16.f16.f32 "
        "{%0,%1,%2,%3}, {%4,%5,%6,%7}, {%8,%9}, {%0,%1,%2,%3};"
        : "+f"(d[0]), "+f"(d[1]), "+f"(d[2]), "+f"(d[3])
        : "r"(a[0]), "r"(a[1]), "r"(a[2]), "r"(a[3]), "r"(b[0]), "r"(b[1]));
}
__device__ __forceinline__ void ldsm_x4(uint32_t& r0, uint32_t& r1, uint32_t& r2,
                                        uint32_t& r3, uint32_t addr) {
    asm volatile("ldmatrix.sync.aligned.m8n8.x4.shared.b16 {%0,%1,%2,%3}, [%4];"
                 : "=r"(r0), "=r"(r1), "=r"(r2), "=r"(r3) : "r"(addr));
}
__device__ __forceinline__ void cp_async16(uint32_t saddr, const void* gaddr, int src_bytes) {
    asm volatile("cp.async.cg.shared.global [%0], [%1], 16, %2;"
                 :: "r"(saddr), "l"(gaddr), "r"(src_bytes));
}
#define CP_COMMIT() asm volatile("cp.async.commit_group;" ::: "memory")
#define CP_WAIT(n)  asm volatile("cp.async.wait_group %0;" :: "n"(n) : "memory")

// ============================ CSR build ============================
__global__ void zero_deg_kernel() {
    int i = blockIdx.x * blockDim.x + threadIdx.x;
    if (i < N_NODES) g_deg[i] = 0;
}
__global__ void count_kernel(const int* __restrict__ ei) {
    int idx = blockIdx.x * blockDim.x + threadIdx.x;
    if (idx >= E_TOT) return;
    int dst = (idx < N_EDGES) ? ei[N_EDGES + idx] : (idx - N_EDGES);
    atomicAdd(&g_deg[dst], 1);
}
__global__ void scan_kernel() {
    __shared__ int sums[1024];
    const int per = (N_NODES + 1023) / 1024;
    int t  = threadIdx.x;
    int lo = t * per;
    int hi = min(lo + per, N_NODES);
    int s = 0;
    for (int i = lo; i < hi; i++) s += g_deg[i];
    sums[t] = s;
    __syncthreads();
    if (t == 0) {
        int run = 0;
        for (int i = 0; i < 1024; i++) { int v = sums[i]; sums[i] = run; run += v; }
        g_rowptr[N_NODES] = run;
    }
    __syncthreads();
    int run = sums[t];
    for (int i = lo; i < hi; i++) {
        g_rowptr[i] = run;
        g_rowcur[i] = run;
        run += g_deg[i];
    }
}
__global__ void fill_kernel(const int* __restrict__ ei) {
    int idx = blockIdx.x * blockDim.x + threadIdx.x;
    if (idx >= E_TOT) return;
    int src, dst;
    if (idx < N_EDGES) { src = ei[idx]; dst = ei[N_EDGES + idx]; }
    else               { src = dst = idx - N_EDGES; }
    int pos = atomicAdd(&g_rowcur[dst], 1);
    g_srclist[pos] = src;
}

// ============================ fp16 hi/lo conversions ============================
__global__ void convert_x_kernel(const float* __restrict__ x) {
    int idx = blockIdx.x * blockDim.x + threadIdx.x;
    if (idx >= N_NODES * KP0) return;
    int n = idx >> 7, k = idx & (KP0 - 1);
    float v = (k < 69) ? x[n * 69 + k] : 0.f;
    __half h = __float2half_rn(v);
    g_Ahi[idx] = h;
    g_Alo[idx] = __float2half_rn(v - __half2float(h));
}
__global__ void convert_w_all_kernel(const float* __restrict__ W0,
                                     const float* __restrict__ W1,
                                     const float* __restrict__ W2) {
    int idx = blockIdx.x * blockDim.x + threadIdx.x;
    if (idx >= WTOT) return;
    const float* W;
    int K, Kp, off;
    if (idx < WOFF1)      { W = W0; K = 69;   Kp = KP0;  off = 0; }
    else if (idx < WOFF2) { W = W1; K = FDIM; Kp = FDIM; off = WOFF1; }
    else                  { W = W2; K = FDIM; Kp = FDIM; off = WOFF2; }
    int li = idx - off;
    int n = li / Kp, k = li % Kp;
    float v = (k < K) ? W[(size_t)k * FDIM + n] : 0.f;
    __half h = __float2half_rn(v);
    g_Wthi[idx] = h;
    g_Wtlo[idx] = __float2half_rn(v - __half2float(h));
}

// ============================ fp16 3-term warp-MMA GEMM + fused alpha ============
// BK=32 + reg-lean inner loop -> 2 CTAs/SM
#define BM 128
#define BN 128
#define BK 32
#define TSTRIDE 40
#define TILE_HALFS (128 * TSTRIDE)
#define BUF_HALFS (4 * TILE_HALFS)
#define SMEM_GEMM (2 * BUF_HALFS * 2 + 128 * 4 * 4)   // 81920 + 2048 B

__global__ __launch_bounds__(256, 2) void mma_gemm_kernel(
    const __half* __restrict__ Ahi, const __half* __restrict__ Alo,
    const __half* __restrict__ Bhi, const __half* __restrict__ Blo,
    float* __restrict__ C, const float* __restrict__ aSrc, const float* __restrict__ aDst,
    int nrows, int Kp)
{
    extern __shared__ __half smh[];
    float* salpha = (float*)(smh + 2 * BUF_HALFS);   // [128][2 heads][2 (src,dst)]

    const int tid  = threadIdx.x;
    const int wid  = tid >> 5;
    const int lane = tid & 31;
    const int gid  = lane >> 2;
    const int tig  = lane & 3;
    const int warp_m = wid >> 2;
    const int warp_n = wid & 3;
    const int rowBase = blockIdx.y * BM;
    const int nBase   = blockIdx.x * BN;

    const int nch = Kp / BK;

    float acc[4][4][4];
#pragma unroll
    for (int i = 0; i < 4; i++)
#pragma unroll
        for (int j = 0; j < 4; j++)
#pragma unroll
            for (int q = 0; q < 4; q++) acc[i][j][q] = 0.f;

    // loader: row = tid>>1 (0..127), seg = tid&1 (16 halfs = 32 B each)
    const int lrow = tid >> 1, lseg = tid & 1;
    const int arow = rowBase + lrow;
    const int aok  = (arow < nrows) ? 16 : 0;
    const __half* gAhi = Ahi + (size_t)(aok ? arow : 0) * Kp + lseg * 16;
    const __half* gAlo = Alo + (size_t)(aok ? arow : 0) * Kp + lseg * 16;
    const __half* gBhi = Bhi + (size_t)(nBase + lrow) * Kp + lseg * 16;
    const __half* gBlo = Blo + (size_t)(nBase + lrow) * Kp + lseg * 16;
    const uint32_t sbase = smem_u32(smh);
    const uint32_t sdst = sbase + (lrow * TSTRIDE + lseg * 16) * 2;

    // ldmatrix per-lane addresses (bytes)
    const int aoff = ((warp_m * 64 + (lane & 15)) * TSTRIDE + (lane >> 4) * 8) * 2;
    const int boff = ((warp_n * 32 + (lane >> 4) * 8 + (lane & 7)) * TSTRIDE
                      + ((lane >> 3) & 1) * 8) * 2;

    auto loadChunk = [&](int ic, int buf) {
        const int k0 = ic * BK;
        const uint32_t b = sdst + buf * (BUF_HALFS * 2);
#pragma unroll
        for (int j = 0; j < 2; j++)
            cp_async16(b + j * 16, gAhi + k0 + j * 8, aok);
#pragma unroll
        for (int j = 0; j < 2; j++)
            cp_async16(b + TILE_HALFS * 2 + j * 16, gAlo + k0 + j * 8, aok);
#pragma unroll
        for (int j = 0; j < 2; j++)
            cp_async16(b + TILE_HALFS * 4 + j * 16, gBhi + k0 + j * 8, 16);
#pragma unroll
        for (int j = 0; j < 2; j++)
            cp_async16(b + TILE_HALFS * 6 + j * 16, gBlo + k0 + j * 8, 16);
        CP_COMMIT();
    };

    loadChunk(0, 0);
    if (tid < 128) {
        salpha[tid * 4 + 0] = 0.f; salpha[tid * 4 + 1] = 0.f;
        salpha[tid * 4 + 2] = 0.f; salpha[tid * 4 + 3] = 0.f;
    }

    for (int ic = 0; ic < nch; ic++) {
        if (ic + 1 < nch) { loadChunk(ic + 1, (ic + 1) & 1); CP_WAIT(1); }
        else              { CP_WAIT(0); }
        __syncthreads();

        const uint32_t asHb = sbase + (ic & 1) * (BUF_HALFS * 2);
        const uint32_t asLb = asHb + TILE_HALFS * 2;
        const uint32_t bsHb = asHb + 2 * TILE_HALFS * 2;
        const uint32_t bsLb = asHb + 3 * TILE_HALFS * 2;

#pragma unroll
        for (int kk = 0; kk < BK; kk += 16) {
            uint32_t bhi[4][2], blo[4][2];
            ldsm_x4(bhi[0][0], bhi[0][1], bhi[1][0], bhi[1][1], bsHb + boff + kk * 2);
            ldsm_x4(bhi[2][0], bhi[2][1], bhi[3][0], bhi[3][1],
                    bsHb + boff + (16 * TSTRIDE + kk) * 2);
            ldsm_x4(blo[0][0], blo[0][1], blo[1][0], blo[1][1], bsLb + boff + kk * 2);
            ldsm_x4(blo[2][0], blo[2][1], blo[3][0], blo[3][1],
                    bsLb + boff + (16 * TSTRIDE + kk) * 2);
            // per-mt: A frags live only inside this iteration (reg pressure)
#pragma unroll
            for (int mt = 0; mt < 4; mt++) {
                uint32_t ahi[4], alo[4];
                ldsm_x4(ahi[0], ahi[1], ahi[2], ahi[3],
                        asHb + aoff + (mt * 16 * TSTRIDE + kk) * 2);
                ldsm_x4(alo[0], alo[1], alo[2], alo[3],
                        asLb + aoff + (mt * 16 * TSTRIDE + kk) * 2);
#pragma unroll
                for (int nt = 0; nt < 4; nt++)
                    mma_f16(acc[mt][nt], ahi, bhi[nt]);
#pragma unroll
                for (int nt = 0; nt < 4; nt++)
                    mma_f16(acc[mt][nt], ahi, blo[nt]);
#pragma unroll
                for (int nt = 0; nt < 4; nt++)
                    mma_f16(acc[mt][nt], alo, bhi[nt]);
            }
        }
        __syncthreads();
    }

    // ---- epilogue: store C + fused alpha partial dots ----
    const int hl = warp_n >> 1;
    float s1[4][2], s2[4][2];
#pragma unroll
    for (int mt = 0; mt < 4; mt++) { s1[mt][0]=0.f; s1[mt][1]=0.f; s2[mt][0]=0.f; s2[mt][1]=0.f; }

#pragma unroll
    for (int mt = 0; mt < 4; mt++) {
        int r0 = rowBase + warp_m * 64 + mt * 16 + gid;
        int r1 = r0 + 8;
#pragma unroll
        for (int nt = 0; nt < 4; nt++) {
            int col = nBase + warp_n * 32 + nt * 8 + 2 * tig;
            float2 aS2 = *(const float2*)(aSrc + col);
            float2 aD2 = *(const float2*)(aDst + col);
            if (r0 < nrows)
                *(float2*)(C + (size_t)r0 * FDIM + col) =
                    make_float2(acc[mt][nt][0], acc[mt][nt][1]);
            if (r1 < nrows)
                *(float2*)(C + (size_t)r1 * FDIM + col) =
                    make_float2(acc[mt][nt][2], acc[mt][nt][3]);
            s1[mt][0] += acc[mt][nt][0] * aS2.x + acc[mt][nt][1] * aS2.y;
            s2[mt][0] += acc[mt][nt][0] * aD2.x + acc[mt][nt][1] * aD2.y;
            s1[mt][1] += acc[mt][nt][2] * aS2.x + acc[mt][nt][3] * aS2.y;
            s2[mt][1] += acc[mt][nt][2] * aD2.x + acc[mt][nt][3] * aD2.y;
        }
    }
#pragma unroll
    for (int mt = 0; mt < 4; mt++)
#pragma unroll
        for (int j = 0; j < 2; j++) {
            s1[mt][j] += __shfl_down_sync(0xffffffffu, s1[mt][j], 2, 4);
            s1[mt][j] += __shfl_down_sync(0xffffffffu, s1[mt][j], 1, 4);
            s2[mt][j] += __shfl_down_sync(0xffffffffu, s2[mt][j], 2, 4);
            s2[mt][j] += __shfl_down_sync(0xffffffffu, s2[mt][j], 1, 4);
        }
    if (tig == 0) {
#pragma unroll
        for (int mt = 0; mt < 4; mt++) {
            int lr0 = warp_m * 64 + mt * 16 + gid;
            atomicAdd(&salpha[lr0 * 4 + hl * 2 + 0], s1[mt][0]);
            atomicAdd(&salpha[lr0 * 4 + hl * 2 + 1], s2[mt][0]);
            atomicAdd(&salpha[(lr0 + 8) * 4 + hl * 2 + 0], s1[mt][1]);
            atomicAdd(&salpha[(lr0 + 8) * 4 + hl * 2 + 1], s2[mt][1]);
        }
    }
    __syncthreads();
    if (tid < 128) {
        int grow = rowBase + tid;
        if (grow < nrows) {
            int hbase = (nBase >> 6);
            g_asrc[grow * HEADS + hbase]     = salpha[tid * 4 + 0];
            g_adst[grow * HEADS + hbase]     = salpha[tid * 4 + 1];
            g_asrc[grow * HEADS + hbase + 1] = salpha[tid * 4 + 2];
            g_adst[grow * HEADS + hbase + 1] = salpha[tid * 4 + 3];
        }
    }
}

// ---------------- fused online-softmax aggregation (R10 core) ----------------
#define AGG_CHUNK 256
__global__ __launch_bounds__(128) void aggregate_kernel(
    const float* __restrict__ h, const float* __restrict__ bias,
    __half* __restrict__ outHi, __half* __restrict__ outLo,
    const float* __restrict__ predW, const float* __restrict__ predb,
    float* __restrict__ out, int mode)
{
    int d = blockIdx.x;
    int t = threadIdx.x;            // 128 threads, 4 channels each
    int head = t >> 4;
    int start = g_rowptr[d], end = g_rowptr[d + 1];
    float adst_v = g_adst[d * HEADS + head];

    __shared__ int ssrc[AGG_CHUNK];
    __shared__ float spred[3];

    float m = -INFINITY, denom = 0.f;
    float4 acc = make_float4(0.f, 0.f, 0.f, 0.f);

    for (int base = start; base < end; base += AGG_CHUNK) {
        int cnt = min(AGG_CHUNK, end - base);
        __syncthreads();
        for (int i = t; i < cnt; i += 128) ssrc[i] = g_srclist[base + i];
        if (t < 3 && base == start) spred[t] = 0.f;
        __syncthreads();
#pragma unroll 4
        for (int i = 0; i < cnt; i++) {
            int s = ssrc[i];
            float e = g_asrc[s * HEADS + head] + adst_v;
            e = (e > 0.f) ? e : NEG_SLOPE * e;
            if (e > m) {
                float sc = __expf(m - e);
                m = e;
                denom *= sc;
                acc.x *= sc; acc.y *= sc; acc.z *= sc; acc.w *= sc;
            }
            float w = __expf(e - m);
            denom += w;
            float4 hv = *(const float4*)(h + (size_t)s * FDIM + t * 4);
            acc.x += w * hv.x; acc.y += w * hv.y;
            acc.z += w * hv.z; acc.w += w * hv.w;
        }
    }

    float inv = 1.f / (denom + 1e-16f);
    float4 b4 = *(const float4*)(bias + t * 4);
    float4 o;
    o.x = acc.x * inv + b4.x; o.y = acc.y * inv + b4.y;
    o.z = acc.z * inv + b4.z; o.w = acc.w * inv + b4.w;

    if (mode == 0) {
        o.x = fmaxf(o.x, 0.f); o.y = fmaxf(o.y, 0.f);
        o.z = fmaxf(o.z, 0.f); o.w = fmaxf(o.w, 0.f);
        size_t idx = (size_t)d * FDIM + t * 4;
        __half hx = __float2half_rn(o.x), hy = __float2half_rn(o.y);
        __half hz = __float2half_rn(o.z), hw = __float2half_rn(o.w);
        __half2* ph = (__half2*)(outHi + idx);
        ph[0] = __halves2half2(hx, hy);
        ph[1] = __halves2half2(hz, hw);
        __half2* pl = (__half2*)(outLo + idx);
        pl[0] = __halves2half2(__float2half_rn(o.x - __half2float(hx)),
                               __float2half_rn(o.y - __half2float(hy)));
        pl[1] = __halves2half2(__float2half_rn(o.z - __half2float(hz)),
                               __float2half_rn(o.w - __half2float(hw)));
    } else {
        int c0 = t * 4;
        float p0 = o.x * predW[(c0+0)*3+0] + o.y * predW[(c0+1)*3+0]
                 + o.z * predW[(c0+2)*3+0] + o.w * predW[(c0+3)*3+0];
        float p1 = o.x * predW[(c0+0)*3+1] + o.y * predW[(c0+1)*3+1]
                 + o.z * predW[(c0+2)*3+1] + o.w * predW[(c0+3)*3+1];
        float p2 = o.x * predW[(c0+0)*3+2] + o.y * predW[(c0+1)*3+2]
                 + o.z * predW[(c0+2)*3+2] + o.w * predW[(c0+3)*3+2];
#pragma unroll
        for (int off = 16; off > 0; off >>= 1) {
            p0 += __shfl_down_sync(0xffffffffu, p0, off);
            p1 += __shfl_down_sync(0xffffffffu, p1, off);
            p2 += __shfl_down_sync(0xffffffffu, p2, off);
        }
        if ((t & 31) == 0) {
            atomicAdd(&spred[0], p0);
            atomicAdd(&spred[1], p1);
            atomicAdd(&spred[2], p2);
        }
        __syncthreads();
        if (t < 3) out[d * 3 + t] = spred[t] + predb[t];
    }
}

// ---------------- launch ----------------
extern "C" void kernel_launch(void* const* d_in, const int* in_sizes, int n_in,
                              void* d_out, int out_size)
{
    const float* x     = (const float*)d_in[0];   // [N,69]
    const int*   ei    = (const int*)  d_in[1];   // [2,E]
    const float* W[3]    = {(const float*)d_in[3],  (const float*)d_in[7],  (const float*)d_in[11]};
    const float* aS[3]   = {(const float*)d_in[4],  (const float*)d_in[8],  (const float*)d_in[12]};
    const float* aD[3]   = {(const float*)d_in[5],  (const float*)d_in[9],  (const float*)d_in[13]};
    const float* bb[3]   = {(const float*)d_in[6],  (const float*)d_in[10], (const float*)d_in[14]};
    const float* predW = (const float*)d_in[15];
    const float* predb = (const float*)d_in[16];
    float* out = (float*)d_out;

    float*  hA;  cudaGetSymbolAddress((void**)&hA,  g_hA);
    __half* Ahi; cudaGetSymbolAddress((void**)&Ahi, g_Ahi);
    __half* Alo; cudaGetSymbolAddress((void**)&Alo, g_Alo);
    __half* Whi; cudaGetSymbolAddress((void**)&Whi, g_Wthi);
    __half* Wlo; cudaGetSymbolAddress((void**)&Wlo, g_Wtlo);

    cudaFuncSetAttribute(mma_gemm_kernel,
                         cudaFuncAttributeMaxDynamicSharedMemorySize, SMEM_GEMM);

    const int  K_in[3] = {KP0, FDIM, FDIM};
    const int  woff[3] = {WOFF0, WOFF1, WOFF2};
    dim3 ggrid(FDIM / BN, (N_NODES + BM - 1) / BM);

    // launches 1-4: zero, convert_x, convert_w_all, GEMM layer 0 (GEMM = #4 for ncu)
    zero_deg_kernel<<<(N_NODES + 255) / 256, 256>>>();
    convert_x_kernel<<<(N_NODES * KP0 + 255) / 256, 256>>>(x);
    convert_w_all_kernel<<<(WTOT + 255) / 256, 256>>>(W[0], W[1], W[2]);
    mma_gemm_kernel<<<ggrid, 256, SMEM_GEMM>>>(Ahi, Alo, Whi + woff[0], Wlo + woff[0],
                                               hA, aS[0], aD[0], N_NODES, K_in[0]);
    // CSR build (needed only by aggregate)
    count_kernel<<<(E_TOT + 255) / 256, 256>>>(ei);
    scan_kernel<<<1, 1024>>>();
    fill_kernel<<<(E_TOT + 255) / 256, 256>>>(ei);

    aggregate_kernel<<<N_NODES, 128>>>(hA, bb[0], Ahi, Alo, predW, predb, out, 0);

    for (int l = 1; l < 3; l++) {
        mma_gemm_kernel<<<ggrid, 256, SMEM_GEMM>>>(Ahi, Alo, Whi + woff[l], Wlo + woff[l],
                                                   hA, aS[l], aD[l], N_NODES, K_in[l]);
        aggregate_kernel<<<N_NODES, 128>>>(hA, bb[l], Ahi, Alo,
                                           predW, predb, out, (l == 2) ? 1 : 0);
    }
}